// round 11
// baseline (speedup 1.0000x reference)
#include <cuda_runtime.h>
#include <math.h>
#include <stdint.h>

// Problem constants (match reference)
#define N_INPUTS 2048
#define UNITS    2048
#define L        8
#define FANIN    4096
#define TOTAL    (N_INPUTS + L * UNITS)   // 18432

// Persistent-kernel decomposition
#define NBLK     256                      // co-resident (>=2 blocks/SM, 148 SMs)
#define TPB      256
#define KSPLIT   128                      // k-chunks per layer
#define KCHUNK   (FANIN / KSPLIT)         // 32 rows per chunk
#define NBAR     L
#define CAP      16                       // deferred rows staged in smem
#define DSMEM    (CAP * 1024 * 4)         // 64KB: CAP rows x 1024 units

// Scratch (device globals: allocation-free per harness rules)
__device__ float g_state[TOTAL];                    // shared "outputs" vector
__device__ float g_pt[2][UNITS * KSPLIT];           // TRANSPOSED partials [u][s]
__device__ int   g_bar[NBAR];

__global__ void init_kernel(const float* __restrict__ x) {
    int i = blockIdx.x * blockDim.x + threadIdx.x;
    if (i < TOTAL) g_state[i] = (i < N_INPUTS) ? x[i] : 0.0f;
    if (i < NBAR)  g_bar[i] = 0;
}

__device__ __forceinline__ float ldcg_f(const float* p) {
    float v; asm volatile("ld.global.cg.f32 %0, [%1];" : "=f"(v) : "l"(p)); return v;
}
__device__ __forceinline__ float4 ldcg_f4(const float4* p) {
    float4 v;
    asm volatile("ld.global.cg.v4.f32 {%0,%1,%2,%3}, [%4];"
                 : "=f"(v.x), "=f"(v.y), "=f"(v.z), "=f"(v.w) : "l"(p));
    return v;
}
__device__ __forceinline__ void bar_arrive(int* p) {
    asm volatile("red.release.gpu.global.add.s32 [%0], 1;" :: "l"(p) : "memory");
}
__device__ __forceinline__ int ld_acq(const int* p) {
    int v; asm volatile("ld.acquire.gpu.global.s32 %0, [%1];" : "=r"(v) : "l"(p) : "memory");
    return v;
}
__device__ __forceinline__ void pf_l2(const void* p) {
    asm volatile("prefetch.global.L2 [%0];" :: "l"(p));
}
__device__ __forceinline__ uint32_t smem_u32(const void* p) {
    uint32_t a;
    asm("{ .reg .u64 t; cvta.to.shared.u64 t, %1; cvt.u32.u64 %0, t; }"
        : "=r"(a) : "l"(p));
    return a;
}
__device__ __forceinline__ void cp_async16(uint32_t dst, const void* src) {
    asm volatile("cp.async.cg.shared.global [%0], [%1], 16;" :: "r"(dst), "l"(src));
}

// Coalesced reduction of one unit's KSPLIT partials (transposed buffer):
// warp reads 32 consecutive float4s (512B), fixed order -> deterministic.
__device__ __forceinline__ float reduce_t(const float* buf, int u, int lane) {
    const float4 v = ldcg_f4(reinterpret_cast<const float4*>(buf) + u * (KSPLIT / 4) + lane);
    float a = (v.x + v.y) + (v.z + v.w);
    #pragma unroll
    for (int off = 16; off > 0; off >>= 1) a += __shfl_xor_sync(0xFFFFFFFFu, a, off);
    return a;
}

// Pipelined persistent kernel. Block bid: kc=bid>>1 (32-row k-chunk),
// uh=bid&1 (unit half). Per phase i (serial window):
//   finalize layer i-1 -> g_state segment i
//   deferred rows of layer i: multipliers resolved now, W read from SMEM
//   (staged last phase via cp.async) -> finish acc; store partials; ARRIVE.
// Overlap window: build layer i+1 lists; cp.async its deferred W rows into
// smem; bulk-stream its already-published rows into registers; WAIT.
__global__ __launch_bounds__(TPB, 2) void net_kernel(
    const float* __restrict__ Ws,        // [L, FANIN, UNITS]
    const int*   __restrict__ node_inds, // [L, FANIN]
    const float* __restrict__ bs,        // [L, UNITS]
    float*       __restrict__ out)       // [UNITS]
{
    extern __shared__ __align__(16) float4 sW4[];   // [CAP][256] staged W rows

    __shared__ int   s_bind[KCHUNK], s_brow[KCHUNK];   // bulk: state idx, row
    __shared__ int   s_dind[KCHUNK], s_drow[KCHUNK];   // deferred: state idx, row
    __shared__ float lval[KCHUNK];
    __shared__ int   s_nb, s_nd;

    const int tid   = threadIdx.x;
    const int bid   = blockIdx.x;
    const int kc    = bid >> 1;
    const int uh    = bid & 1;
    const int warp  = tid >> 5;
    const int lane  = tid & 31;
    const int myu   = bid * 8 + warp;        // this warp's finalize unit
    const int ubase = uh * 1024 + 4 * tid;   // this thread's 4 units

    const uint32_t sW4_base = smem_u32(sW4);

    float4 acc = make_float4(0.f, 0.f, 0.f, 0.f);

    for (int i = 0; i < L; ++i) {
        const int slim = i * 2048;           // segment-i base (on-the-fly reduce)
        const int pb   = (i - 1) & 1;
        const float4* W4i = reinterpret_cast<const float4*>(Ws + (size_t)i * FANIN * UNITS)
                          + (size_t)kc * KCHUNK * 512 + uh * 256 + tid;

        // ---- finalize layer i-1 -> g_state segment i (published at bar_i) ----
        if (i > 0) {
            const float a = reduce_t(g_pt[pb], myu, lane);
            if (lane == 0) g_state[slim + myu] = tanhf(a + bs[(i - 1) * UNITS + myu]);
        }

        // ---- layer 0: build its (all-deferred) list here; no staging ----
        if (i == 0) {
            if (warp == 0) {
                const int ind = node_inds[kc * KCHUNK + lane];
                const bool d = (ind < 2048);
                const unsigned m = __ballot_sync(0xFFFFFFFFu, d);
                if (d) {
                    const int j = __popc(m & ((1u << lane) - 1));
                    s_dind[j] = ind; s_drow[j] = lane;
                }
                if (lane == 0) s_nd = __popc(m);
            }
            __syncthreads();
        }
        const int nd = s_nd;

        // ---- fill deferred multipliers ----
        for (int j = warp; j < nd; j += 8) {
            const int ind = s_dind[j];
            float v;
            if (i > 0 && ind >= slim) {
                const int u = ind - slim;
                const float a = reduce_t(g_pt[pb], u, lane);
                v = tanhf(a + bs[(i - 1) * UNITS + u]);
            } else {
                v = (lane == 0) ? ldcg_f(&g_state[ind]) : 0.0f;
            }
            if (lane == 0) lval[j] = v;
        }
        __syncthreads();

        // ---- deferred FMAs: W from smem (staged last phase) ----
        if (i > 0) asm volatile("cp.async.wait_group 0;" ::: "memory");
        for (int j = 0; j < nd; ++j) {
            const float s = lval[j];
            float4 w;
            if (i > 0 && j < CAP) w = sW4[j * 256 + tid];
            else                  w = W4i[(size_t)s_drow[j] * 512];   // L2-hot / layer 0
            acc.x = fmaf(s, w.x, acc.x);
            acc.y = fmaf(s, w.y, acc.y);
            acc.z = fmaf(s, w.z, acc.z);
            acc.w = fmaf(s, w.w, acc.w);
        }

        // ---- store transposed partials for layer i ----
        float* pt = g_pt[i & 1];
        pt[(size_t)(ubase + 0) * KSPLIT + kc] = acc.x;
        pt[(size_t)(ubase + 1) * KSPLIT + kc] = acc.y;
        pt[(size_t)(ubase + 2) * KSPLIT + kc] = acc.z;
        pt[(size_t)(ubase + 3) * KSPLIT + kc] = acc.w;
        __syncthreads();

        if (tid == 0) bar_arrive(&g_bar[i]);

        // ---- overlap window: lists + staging + bulk stream for layer i+1 ----
        const int plim = (i == 0) ? 2048 : slim;     // published segments
        float4 nacc = make_float4(0.f, 0.f, 0.f, 0.f);
        if (i + 1 < L) {
            const int nlim = (i + 2) * 2048;
            const int* ninds = node_inds + (i + 1) * FANIN + kc * KCHUNK;
            if (warp == 0) {
                const int ind = ninds[lane];
                const bool lv = (ind < nlim);
                const bool p  = (ind < plim);
                const unsigned mb = __ballot_sync(0xFFFFFFFFu, p);
                const unsigned md = __ballot_sync(0xFFFFFFFFu, lv && !p);
                if (p) {
                    const int j = __popc(mb & ((1u << lane) - 1));
                    s_bind[j] = ind; s_brow[j] = lane;
                }
                if (lv && !p) {
                    const int j = __popc(md & ((1u << lane) - 1));
                    s_dind[j] = ind; s_drow[j] = lane;
                }
                if (lane == 0) { s_nb = __popc(mb); s_nd = __popc(md); }
            }
            __syncthreads();
            const int nb = s_nb;
            const int nd2 = s_nd;

            const float4* W4n = reinterpret_cast<const float4*>(
                                    Ws + (size_t)(i + 1) * FANIN * UNITS)
                              + (size_t)kc * KCHUNK * 512 + uh * 256 + tid;

            // Stage deferred W rows into smem via cp.async (background copy;
            // completion only needed after next phase's barrier wait).
            const int nst = (nd2 < CAP) ? nd2 : CAP;
            for (int j = 0; j < nst; ++j) {
                cp_async16(sW4_base + (uint32_t)(j * 256 + tid) * 16u,
                           W4n + (size_t)s_drow[j] * 512);
            }
            asm volatile("cp.async.commit_group;" ::: "memory");
            // Overflow rows: at least get them L2-hot.
            for (int j = CAP + warp; j < nd2; j += 8) {
                const float* r = Ws + (size_t)(i + 1) * FANIN * UNITS
                               + (size_t)(kc * KCHUNK + s_drow[j]) * UNITS + uh * 1024;
                pf_l2((const char*)r + lane * 128);
            }

            // Bulk multipliers (published segments) then bulk FMA stream.
            if (tid < nb) lval[tid] = ldcg_f(&g_state[s_bind[tid]]);
            __syncthreads();
            #pragma unroll 4
            for (int j = 0; j < nb; ++j) {
                const float s = lval[j];
                const float4 w = W4n[(size_t)s_brow[j] * 512];
                nacc.x = fmaf(s, w.x, nacc.x);
                nacc.y = fmaf(s, w.y, nacc.y);
                nacc.z = fmaf(s, w.z, nacc.z);
                nacc.w = fmaf(s, w.w, nacc.w);
            }
        }

        // ---- wait for all blocks (partials_i + segment i published) ----
        if (tid == 0) {
            while (ld_acq(&g_bar[i]) < NBLK) { __nanosleep(16); }
        }
        __syncthreads();

        acc = nacc;
    }

    // ---- final output: finalize layer L-1 ----
    {
        const float a = reduce_t(g_pt[(L - 1) & 1], myu, lane);
        if (lane == 0) out[myu] = tanhf(a + bs[(L - 1) * UNITS + myu]);
    }
}

extern "C" void kernel_launch(void* const* d_in, const int* in_sizes, int n_in,
                              void* d_out, int out_size) {
    const float* x         = (const float*)d_in[0];  // [2048] f32
    const int*   node_inds = (const int*)  d_in[1];  // [L, FANIN] i32
    const float* Ws        = (const float*)d_in[2];  // [L, FANIN, UNITS] f32
    const float* bs        = (const float*)d_in[3];  // [L, UNITS] f32
    float*       out       = (float*)d_out;          // [2048] f32

    cudaFuncSetAttribute(net_kernel,
                         cudaFuncAttributeMaxDynamicSharedMemorySize, DSMEM);

    init_kernel<<<(TOTAL + 255) / 256, 256>>>(x);
    net_kernel<<<NBLK, TPB, DSMEM>>>(Ws, node_inds, bs, out);
}